// round 1
// baseline (speedup 1.0000x reference)
#include <cuda_runtime.h>
#include <cuda_fp16.h>

// Problem dims (fixed by the dataset)
#define B_ 64
#define T_ 2048
#define I_ 256
#define H_ 256
#define G4_ 1024  // 4*H

// Scratch for the input projection xz = x@Wx + b : [B,T,4H] fp32 (537 MB).
// __device__ global array is the sanctioned scratch mechanism (no allocs allowed).
__device__ float g_xz[(size_t)B_ * T_ * G4_];

// ---------------------------------------------------------------------------
// Kernel 1: xz[m][n] = sum_k x[m][k] * Wx[k][n] + b[n]
// M = B*T = 131072, K = 256, N = 1024. fp32 tiled GEMM.
// BM=128, BN=128, BK=16, 256 threads, 8x8 register tile per thread.
// ---------------------------------------------------------------------------
__global__ __launch_bounds__(256) void gemm_xz_kernel(
    const float* __restrict__ x, const float* __restrict__ Wx,
    const float* __restrict__ bias)
{
    const int BK = 16;
    __shared__ float As[16][130];   // [k][m], padded stride 130 -> conflict-free transpose stores
    __shared__ float Bs[16][128];   // [k][n]

    const int tid = threadIdx.x;
    const int m0 = blockIdx.y * 128;
    const int n0 = blockIdx.x * 128;
    const int ty = tid >> 4;   // 0..15 (m group)
    const int tx = tid & 15;   // 0..15 (n group)

    float acc[8][8];
#pragma unroll
    for (int i = 0; i < 8; i++)
#pragma unroll
        for (int j = 0; j < 8; j++) acc[i][j] = 0.f;

    const int arow = tid >> 2;         // 0..63 (+64)
    const int akq  = tid & 3;          // which float4 along k
    const int bk   = tid >> 5;         // 0..7 (+8)
    const int bn4  = (tid & 31) << 2;  // 0..124

    for (int k0 = 0; k0 < 256; k0 += BK) {
        // A tile: 128 rows x 16 k, transposed into As[k][m]
#pragma unroll
        for (int h = 0; h < 2; h++) {
            int row = arow + h * 64;
            float4 v = *reinterpret_cast<const float4*>(&x[(size_t)(m0 + row) * 256 + k0 + akq * 4]);
            As[akq * 4 + 0][row] = v.x;
            As[akq * 4 + 1][row] = v.y;
            As[akq * 4 + 2][row] = v.z;
            As[akq * 4 + 3][row] = v.w;
        }
        // B tile: 16 k x 128 n
#pragma unroll
        for (int h = 0; h < 2; h++) {
            int kk = bk + h * 8;
            float4 v = *reinterpret_cast<const float4*>(&Wx[(size_t)(k0 + kk) * 1024 + n0 + bn4]);
            *reinterpret_cast<float4*>(&Bs[kk][bn4]) = v;
        }
        __syncthreads();

#pragma unroll
        for (int kk = 0; kk < BK; kk++) {
            float a[8], b[8];
#pragma unroll
            for (int i = 0; i < 8; i++) a[i] = As[kk][ty + 16 * i];
#pragma unroll
            for (int j = 0; j < 8; j++) b[j] = Bs[kk][tx + 16 * j];
#pragma unroll
            for (int i = 0; i < 8; i++)
#pragma unroll
                for (int j = 0; j < 8; j++)
                    acc[i][j] = fmaf(a[i], b[j], acc[i][j]);
        }
        __syncthreads();
    }

#pragma unroll
    for (int i = 0; i < 8; i++) {
        int m = m0 + ty + 16 * i;
#pragma unroll
        for (int j = 0; j < 8; j++) {
            int n = n0 + tx + 16 * j;
            g_xz[(size_t)m * 1024 + n] = acc[i][j] + bias[n];
        }
    }
}

// ---------------------------------------------------------------------------
// Kernel 2: LSTM scan. Cluster of 4 CTAs handles 2 batch rows.
// CTA r owns units [64r, 64r+64) of all 4 gates (256 columns of Wh),
// weights cached in SMEM as fp16 (k-pair interleaved), fp32 accumulate.
// One barrier.cluster per timestep; h exchanged via DSMEM stores with
// parity double-buffering. c lives in registers of the 128 updater threads.
// ---------------------------------------------------------------------------
__device__ __forceinline__ float sigf(float z) {
    return 1.0f / (1.0f + __expf(-z));
}

__global__ __launch_bounds__(256, 1) __cluster_dims__(4, 1, 1)
void lstm_scan_kernel(const float* __restrict__ Wh,
                      const float* __restrict__ h0,
                      const float* __restrict__ c0,
                      float* __restrict__ out)
{
    extern __shared__ unsigned char smem[];
    // whs: [128 k2][256 col] half2 (each holds W[2k2][col], W[2k2+1][col])  = 128 KB
    __half2* whs = reinterpret_cast<__half2*>(smem);
    // hs4: [parity 2][128 k2] float4 {h_b0[2k2], h_b1[2k2], h_b0[2k2+1], h_b1[2k2+1]} = 4 KB
    float4* hs4 = reinterpret_cast<float4*>(smem + 128 * 256 * 4);
    // zs: [batch 2][256 col] fp32 = 2 KB
    float* zs = reinterpret_cast<float*>(smem + 128 * 256 * 4 + 4096);

    const int tid = threadIdx.x;
    unsigned int rank;
    asm("mov.u32 %0, %%cluster_ctarank;" : "=r"(rank));
    const int cl = blockIdx.x >> 2;
    const int b0 = cl * 2;

    // Column owned by this thread: gate g = tid>>6, unit u = tid&63
    const int col = ((tid >> 6) << 8) + ((int)rank << 6) + (tid & 63);

    // --- Load Wh slice into SMEM (fp32 -> fp16, k-pair interleaved) ---
    for (int idx = tid; idx < 128 * 256; idx += 256) {
        int k2 = idx >> 8;
        int c  = idx & 255;
        int cc = ((c >> 6) << 8) + ((int)rank << 6) + (c & 63);
        float w0 = Wh[(size_t)(2 * k2) * 1024 + cc];
        float w1 = Wh[(size_t)(2 * k2 + 1) * 1024 + cc];
        whs[idx] = __floats2half2_rn(w0, w1);
    }

    // --- Init h (parity 0) and per-thread cell state ---
    if (tid < 128) {
        int k2 = tid;
        float4 v;
        v.x = h0[(size_t)(b0    ) * 256 + 2 * k2    ];
        v.y = h0[(size_t)(b0 + 1) * 256 + 2 * k2    ];
        v.z = h0[(size_t)(b0    ) * 256 + 2 * k2 + 1];
        v.w = h0[(size_t)(b0 + 1) * 256 + 2 * k2 + 1];
        hs4[k2] = v;
    }
    float c_reg = 0.f;
    int ub = 0, uu = 0, uj = 0;
    if (tid < 128) {
        ub = tid >> 6;            // which of the 2 batches
        uu = tid & 63;            // local unit
        uj = ((int)rank << 6) + uu;  // global unit index
        c_reg = c0[(size_t)(b0 + ub) * 256 + uj];
    }
    const unsigned int hs4_saddr = (unsigned int)__cvta_generic_to_shared(hs4);

    __syncthreads();
    asm volatile("barrier.cluster.arrive.aligned;" ::: "memory");
    asm volatile("barrier.cluster.wait.aligned;" ::: "memory");

    for (int t = 0; t < T_; t++) {
        const int p = t & 1;
        // Prefetch xz for this step (global, latency hidden behind the dot loop)
        const float xzv0 = __ldg(&g_xz[((size_t)(b0    ) * T_ + t) * 1024 + col]);
        const float xzv1 = __ldg(&g_xz[((size_t)(b0 + 1) * T_ + t) * 1024 + col]);

        const float4* hp = hs4 + p * 128;
        float acc0 = 0.f, acc1 = 0.f;
#pragma unroll 8
        for (int k2 = 0; k2 < 128; k2++) {
            float4 hv = hp[k2];                           // broadcast LDS.128
            float2 wf = __half22float2(whs[k2 * 256 + tid]);  // conflict-free LDS.32
            acc0 = fmaf(hv.x, wf.x, acc0);
            acc1 = fmaf(hv.y, wf.x, acc1);
            acc0 = fmaf(hv.z, wf.y, acc0);
            acc1 = fmaf(hv.w, wf.y, acc1);
        }
        zs[tid]       = xzv0 + acc0;
        zs[256 + tid] = xzv1 + acc1;
        __syncthreads();

        if (tid < 128) {
            const float* zb = zs + ub * 256;
            float zi = zb[uu];
            float zf = zb[64 + uu];
            float zg = zb[128 + uu];
            float zo = zb[192 + uu];
            float gi = sigf(zi);
            float gf = sigf(zf);
            float gg = 2.f * sigf(2.f * zg) - 1.f;   // tanh
            float go = sigf(zo);
            c_reg = gf * c_reg + gi * gg;
            float th = 2.f * sigf(2.f * c_reg) - 1.f;
            float h = go * th;

            out[((size_t)(b0 + ub) * T_ + t) * 256 + uj] = h;

            // Scatter h into every cluster CTA's next-parity buffer (incl. self)
            int k = uj;
            int comp = ((k & 1) << 1) + ub;
            unsigned int off = hs4_saddr +
                (unsigned int)((((p ^ 1) * 128 + (k >> 1)) * 16) + comp * 4);
#pragma unroll
            for (unsigned int rr = 0; rr < 4; rr++) {
                unsigned int ra;
                asm("mapa.shared::cluster.u32 %0, %1, %2;" : "=r"(ra) : "r"(off), "r"(rr));
                asm volatile("st.shared::cluster.f32 [%0], %1;" :: "r"(ra), "f"(h));
            }
        }
        // One cluster-wide barrier per step (release/acquire orders the DSMEM stores)
        asm volatile("barrier.cluster.arrive.aligned;" ::: "memory");
        asm volatile("barrier.cluster.wait.aligned;" ::: "memory");
    }
}

// ---------------------------------------------------------------------------
extern "C" void kernel_launch(void* const* d_in, const int* in_sizes, int n_in,
                              void* d_out, int out_size)
{
    const float* x    = (const float*)d_in[0];
    const float* Wx   = (const float*)d_in[1];
    const float* Wh   = (const float*)d_in[2];
    const float* bias = (const float*)d_in[3];
    const float* h0   = (const float*)d_in[4];
    const float* c0   = (const float*)d_in[5];
    float* out = (float*)d_out;

    // Phase 1: input projection
    dim3 g1(1024 / 128, (B_ * T_) / 128);  // (8, 1024)
    gemm_xz_kernel<<<g1, 256>>>(x, Wx, bias);

    // Phase 2: recurrent scan (32 clusters of 4 CTAs)
    const int smem_bytes = 128 * 256 * 4 + 4096 + 2048;  // 137216
    cudaFuncSetAttribute(lstm_scan_kernel,
                         cudaFuncAttributeMaxDynamicSharedMemorySize, smem_bytes);
    lstm_scan_kernel<<<128, 256, smem_bytes>>>(Wh, h0, c0, out);
}